// round 10
// baseline (speedup 1.0000x reference)
#include <cuda_runtime.h>
#include <math.h>

#define NB      8
#define NT      250
#define MTOK    2000          // NB*NT tokens
#define DMODEL  512
#define DINNER  1024
#define DSTATE  64
#define FLATK   120000

// ---------------- scratch (static device globals; no allocation) ------------
__device__ __align__(256) float g_xz[MTOK * 2048];       // in_proj out  (x | z)
__device__ __align__(256) float g_xconv[MTOK * DINNER];  // conv+silu out
__device__ __align__(256) float g_xdbl[MTOK * 160];      // x_proj out (dt|B|C)
__device__ __align__(256) float g_dt[MTOK * DINNER];     // softplus(dt_proj)
__device__ __align__(256) float g_yact[MTOK * DINNER];   // ssm out * silu(z)
__device__ __align__(256) float g_yperm[NB * FLATK];     // selu + permuted
__device__ __align__(256) float g_fc1[NB * 512];

__device__ __forceinline__ float siluf(float x) { return x / (1.f + __expf(-x)); }

// ---------------- generic fp32 GEMM: C[M,N] = A[M,K] * W[N,K]^T -------------
// BM=BN=64, BK=16, 256 threads, 4x4 microtile.
// EPI: 0 = plain store, 1 = atomicAdd (split-K), 2 = selu+permute (out_proj),
//      3 = +bias then softplus (dt path)
template <int EPI>
__global__ void __launch_bounds__(256) gemm64(
    const float* __restrict__ A, const float* __restrict__ W,
    float* __restrict__ C, const float* __restrict__ bias,
    int M, int N, int K, int lda, int ldb, int ldc,
    int klimA, int kChunk)
{
    __shared__ __align__(16) float As[16][68];
    __shared__ __align__(16) float Ws[16][68];
    const int tid = threadIdx.x;
    const int m0  = blockIdx.x * 64;
    const int n0  = blockIdx.y * 64;
    const int kBeg = blockIdx.z * kChunk;
    const int kEnd = min(K, kBeg + kChunk);
    const int lr  = tid >> 2;          // 0..63  tile row for loading
    const int lk  = (tid & 3) << 2;    // 0,4,8,12
    const int ty4 = (tid >> 4) << 2;   // 0..60  output rows
    const int tx4 = (tid & 15) << 2;   // 0..60  output cols

    float acc[4][4];
#pragma unroll
    for (int i = 0; i < 4; i++)
#pragma unroll
        for (int j = 0; j < 4; j++) acc[i][j] = 0.f;

    for (int kc = kBeg; kc < kEnd; kc += 16) {
        const int ak = kc + lk;
        float4 av = make_float4(0.f, 0.f, 0.f, 0.f);
        const int am = m0 + lr;
        if (am < M && ak < klimA)
            av = *(const float4*)(A + (size_t)am * lda + ak);
        As[lk + 0][lr] = av.x; As[lk + 1][lr] = av.y;
        As[lk + 2][lr] = av.z; As[lk + 3][lr] = av.w;

        float4 wv = make_float4(0.f, 0.f, 0.f, 0.f);
        const int wn = n0 + lr;
        if (wn < N)
            wv = *(const float4*)(W + (size_t)wn * ldb + ak);
        Ws[lk + 0][lr] = wv.x; Ws[lk + 1][lr] = wv.y;
        Ws[lk + 2][lr] = wv.z; Ws[lk + 3][lr] = wv.w;
        __syncthreads();

#pragma unroll
        for (int kk = 0; kk < 16; kk++) {
            float4 a = *(const float4*)&As[kk][ty4];
            float4 b = *(const float4*)&Ws[kk][tx4];
            float ar[4] = {a.x, a.y, a.z, a.w};
            float br[4] = {b.x, b.y, b.z, b.w};
#pragma unroll
            for (int i = 0; i < 4; i++)
#pragma unroll
                for (int j = 0; j < 4; j++)
                    acc[i][j] = fmaf(ar[i], br[j], acc[i][j]);
        }
        __syncthreads();
    }

#pragma unroll
    for (int i = 0; i < 4; i++) {
        const int m = m0 + ty4 + i;
        if (m >= M) continue;
#pragma unroll
        for (int j = 0; j < 4; j++) {
            const int n = n0 + tx4 + j;
            if (n >= N) continue;
            float v = acc[i][j];
            if (EPI == 0) {
                C[(size_t)m * ldc + n] = v;
            } else if (EPI == 1) {
                atomicAdd(C + (size_t)m * ldc + n, v);
            } else if (EPI == 2) {
                if (n < 480) {
                    const float SC = 1.0507009873554805f;      // selu scale
                    const float SA = 1.7580993408473766f;      // scale*alpha
                    float s = (v > 0.f) ? SC * v : SA * (expf(v) - 1.f);
                    const int b = m / NT;
                    const int t = m - b * NT;
                    // y[b,t,n] -> perm index b, f=n%24, tp=t*20 + n/24
                    C[(size_t)b * FLATK + (n % 24) * 5000 + t * 20 + (n / 24)] = s;
                }
            } else { // EPI == 3: bias + softplus
                float xv = v + bias[n];
                C[(size_t)m * ldc + n] = (xv > 20.f) ? xv : log1pf(expf(xv));
            }
        }
    }
}

// ---------------- depthwise causal conv (width 4) + SiLU --------------------
__global__ void __launch_bounds__(256) conv_silu_kernel(
    const float* __restrict__ xz, const float* __restrict__ cw,
    const float* __restrict__ cb, float* __restrict__ out)
{
    const int idx = blockIdx.x * 256 + threadIdx.x;   // MTOK*DINNER
    const int d = idx & (DINNER - 1);
    const int m = idx >> 10;
    const int t = m % NT;
    const int mb = m - t;                              // b*NT
    float acc = cb[d];
#pragma unroll
    for (int k = 0; k < 4; k++) {
        const int tt = t - 3 + k;
        if (tt >= 0)
            acc = fmaf(xz[(size_t)(mb + tt) * 2048 + d], cw[d * 4 + k], acc);
    }
    out[idx] = siluf(acc);
}

__global__ void zero_kernel(float* __restrict__ p, int n)
{
    int i = blockIdx.x * 256 + threadIdx.x;
    if (i < n) p[i] = 0.f;
}

// ---------------- selective scan: warp per (b,d), 2 states/lane -------------
__global__ void __launch_bounds__(256) scan_kernel(
    const float* __restrict__ dtb, const float* __restrict__ xdbl,
    const float* __restrict__ xconv, const float* __restrict__ xz,
    const float* __restrict__ A_log, const float* __restrict__ Dp,
    float* __restrict__ yact)
{
    const int warp = threadIdx.x >> 5;
    const int lane = threadIdx.x & 31;
    const int b = blockIdx.x >> 7;                    // /128
    const int d = ((blockIdx.x & 127) << 3) + warp;   // 0..1023

    const float a0 = -__expf(A_log[d * DSTATE + 2 * lane]);
    const float a1 = -__expf(A_log[d * DSTATE + 2 * lane + 1]);
    const float Dv = Dp[d];
    float h0 = 0.f, h1 = 0.f;
    const int mBase = b * NT;

    for (int t = 0; t < NT; t++) {
        const int m = mBase + t;
        const float dtv = __ldg(&dtb[(size_t)m * DINNER + d]);
        const float uv  = __ldg(&xconv[(size_t)m * DINNER + d]);
        const float zv  = __ldg(&xz[(size_t)m * 2048 + DINNER + d]);
        const float2 Bv = *(const float2*)&xdbl[(size_t)m * 160 + 32 + 2 * lane];
        const float2 Cv = *(const float2*)&xdbl[(size_t)m * 160 + 96 + 2 * lane];
        const float dtu = dtv * uv;
        h0 = fmaf(h0, __expf(dtv * a0), dtu * Bv.x);
        h1 = fmaf(h1, __expf(dtv * a1), dtu * Bv.y);
        float p = fmaf(h0, Cv.x, h1 * Cv.y);
#pragma unroll
        for (int off = 16; off; off >>= 1)
            p += __shfl_xor_sync(0xffffffffu, p, off);
        if (lane == 0) {
            const float y = fmaf(uv, Dv, p);
            yact[(size_t)m * DINNER + d] = y * siluf(zv);
        }
    }
}

// ---------------- fc1: [8,120000] x [512,120000]^T, 4 n per block -----------
__global__ void __launch_bounds__(256) fc1_kernel(
    const float* __restrict__ yperm, const float* __restrict__ w1,
    const float* __restrict__ b1, float* __restrict__ out1)
{
    __shared__ __align__(16) float acts[8][1024];
    __shared__ float red2[8][32];
    const int tid = threadIdx.x;
    const int n0  = blockIdx.x * 4;
    const int lane = tid & 31, warp = tid >> 5;

    float acc[8][4];
#pragma unroll
    for (int bi = 0; bi < 8; bi++)
#pragma unroll
        for (int j = 0; j < 4; j++) acc[bi][j] = 0.f;

    for (int k0 = 0; k0 < FLATK; k0 += 1024) {
        const int len = min(1024, FLATK - k0);
        for (int i = tid; i < 8 * 1024; i += 256) {
            const int bb = i >> 10, kk = i & 1023;
            acts[bb][kk] = (kk < len) ? yperm[(size_t)bb * FLATK + k0 + kk] : 0.f;
        }
        __syncthreads();
        const int kk = tid * 4;
        if (kk < len) {
            float4 av[8];
#pragma unroll
            for (int bi = 0; bi < 8; bi++)
                av[bi] = *(const float4*)&acts[bi][kk];
#pragma unroll
            for (int j = 0; j < 4; j++) {
                const float4 wv = *(const float4*)(w1 + (size_t)(n0 + j) * FLATK + k0 + kk);
#pragma unroll
                for (int bi = 0; bi < 8; bi++) {
                    acc[bi][j] = fmaf(av[bi].x, wv.x, acc[bi][j]);
                    acc[bi][j] = fmaf(av[bi].y, wv.y, acc[bi][j]);
                    acc[bi][j] = fmaf(av[bi].z, wv.z, acc[bi][j]);
                    acc[bi][j] = fmaf(av[bi].w, wv.w, acc[bi][j]);
                }
            }
        }
        __syncthreads();
    }

#pragma unroll
    for (int idx = 0; idx < 32; idx++) {
        float v = acc[idx >> 2][idx & 3];
#pragma unroll
        for (int off = 16; off; off >>= 1)
            v += __shfl_xor_sync(0xffffffffu, v, off);
        if (lane == 0) red2[warp][idx] = v;
    }
    __syncthreads();
    if (tid < 32) {
        float s = 0.f;
#pragma unroll
        for (int w = 0; w < 8; w++) s += red2[w][tid];
        const int bi = tid >> 2, j = tid & 3;
        out1[bi * 512 + n0 + j] = s + b1[n0 + j];
    }
}

// ---------------- fc2 -> fc3 -> fc4 (all linear, no activations) ------------
__global__ void __launch_bounds__(256) head_kernel(
    const float* __restrict__ out1,
    const float* __restrict__ w2, const float* __restrict__ b2,
    const float* __restrict__ w3, const float* __restrict__ b3,
    const float* __restrict__ w4, const float* __restrict__ b4,
    float* __restrict__ out)
{
    __shared__ __align__(16) float s1[512];
    __shared__ __align__(16) float s2[256];
    __shared__ __align__(16) float s3[64];
    const int b = blockIdx.x;
    const int tid = threadIdx.x;

    for (int i = tid; i < 512; i += 256) s1[i] = out1[b * 512 + i];
    __syncthreads();
    {
        float a = b2[tid];
        const float4* wr = (const float4*)(w2 + (size_t)tid * 512);
#pragma unroll 4
        for (int k = 0; k < 128; k++) {
            const float4 wv = wr[k];
            const float4 sv = *(const float4*)&s1[k * 4];
            a = fmaf(sv.x, wv.x, a); a = fmaf(sv.y, wv.y, a);
            a = fmaf(sv.z, wv.z, a); a = fmaf(sv.w, wv.w, a);
        }
        s2[tid] = a;
    }
    __syncthreads();
    if (tid < 64) {
        float a = b3[tid];
        const float4* wr = (const float4*)(w3 + (size_t)tid * 256);
#pragma unroll 4
        for (int k = 0; k < 64; k++) {
            const float4 wv = wr[k];
            const float4 sv = *(const float4*)&s2[k * 4];
            a = fmaf(sv.x, wv.x, a); a = fmaf(sv.y, wv.y, a);
            a = fmaf(sv.z, wv.z, a); a = fmaf(sv.w, wv.w, a);
        }
        s3[tid] = a;
    }
    __syncthreads();
    if (tid < 8) {
        float a = b4[tid];
#pragma unroll
        for (int k = 0; k < 64; k++)
            a = fmaf(s3[k], w4[tid * 64 + k], a);
        out[b * 8 + tid] = a;
    }
}

// ---------------------------------------------------------------------------
extern "C" void kernel_launch(void* const* d_in, const int* in_sizes, int n_in,
                              void* d_out, int out_size)
{
    const float* x          = (const float*)d_in[0];   // [8,5000,24]
    const float* in_proj_w  = (const float*)d_in[1];   // [2048,512]
    const float* conv_w     = (const float*)d_in[2];   // [1024,4]
    const float* conv_b     = (const float*)d_in[3];   // [1024]
    const float* x_proj_w   = (const float*)d_in[4];   // [160,1024]
    const float* dt_proj_w  = (const float*)d_in[5];   // [1024,32]
    const float* dt_proj_b  = (const float*)d_in[6];   // [1024]
    const float* A_log      = (const float*)d_in[7];   // [1024,64]
    const float* Dp         = (const float*)d_in[8];   // [1024]
    const float* out_proj_w = (const float*)d_in[9];   // [512,1024]
    const float* fc1_w      = (const float*)d_in[10];  // [512,120000]
    const float* fc1_b      = (const float*)d_in[11];
    const float* fc2_w      = (const float*)d_in[12];  // [256,512]
    const float* fc2_b      = (const float*)d_in[13];
    const float* fc3_w      = (const float*)d_in[14];  // [64,256]
    const float* fc3_b      = (const float*)d_in[15];
    const float* fc4_w      = (const float*)d_in[16];  // [8,64]
    const float* fc4_b      = (const float*)d_in[17];
    float* out = (float*)d_out;

    float *xz, *xconv, *xdbl, *dtb, *yact, *yperm, *fc1o;
    cudaGetSymbolAddress((void**)&xz,    g_xz);
    cudaGetSymbolAddress((void**)&xconv, g_xconv);
    cudaGetSymbolAddress((void**)&xdbl,  g_xdbl);
    cudaGetSymbolAddress((void**)&dtb,   g_dt);
    cudaGetSymbolAddress((void**)&yact,  g_yact);
    cudaGetSymbolAddress((void**)&yperm, g_yperm);
    cudaGetSymbolAddress((void**)&fc1o,  g_fc1);

    // 1) in_proj: xz[2000,2048] = u[2000,480(=K)] * W^T   (pad folded: K=480)
    gemm64<0><<<dim3(32, 32, 1), 256>>>(x, in_proj_w, xz, nullptr,
        MTOK, 2048, 480, 480, DMODEL, 2048, 480, 480);

    // 2) depthwise conv + silu -> xconv[2000,1024]
    conv_silu_kernel<<<(MTOK * DINNER) / 256, 256>>>(xz, conv_w, conv_b, xconv);

    // 3) x_proj (split-K=4, atomicAdd) -> xdbl[2000,160]
    zero_kernel<<<(MTOK * 160 + 255) / 256, 256>>>(xdbl, MTOK * 160);
    gemm64<1><<<dim3(32, 3, 4), 256>>>(xconv, x_proj_w, xdbl, nullptr,
        MTOK, 160, DINNER, DINNER, DINNER, 160, DINNER, 256);

    // 4) dt_proj + bias + softplus -> dt[2000,1024]
    gemm64<3><<<dim3(32, 16, 1), 256>>>(xdbl, dt_proj_w, dtb, dt_proj_b,
        MTOK, DINNER, 32, 160, 32, DINNER, 32, 32);

    // 5) selective scan + gate -> yact[2000,1024]
    scan_kernel<<<NB * 128, 256>>>(dtb, xdbl, xconv, xz, A_log, Dp, yact);

    // 6) out_proj + selu + permute -> yperm[8,120000]
    gemm64<2><<<dim3(32, 8, 1), 256>>>(yact, out_proj_w, yperm, nullptr,
        MTOK, 480, DINNER, DINNER, DINNER, 0, DINNER, DINNER);

    // 7) fc1 -> [8,512]
    fc1_kernel<<<128, 256>>>(yperm, fc1_w, fc1_b, fc1o);

    // 8) fc2/fc3/fc4 -> [8,8]
    head_kernel<<<NB, 256>>>(fc1o, fc2_w, fc2_b, fc3_w, fc3_b, fc4_w, fc4_b, out);

    (void)in_sizes; (void)n_in; (void)out_size;
}